// round 6
// baseline (speedup 1.0000x reference)
#include <cuda_runtime.h>

typedef unsigned long long ull;

// Problem constants
#define BB    64    // batch
#define WDIM  128   // node feature dim (K of projection)
#define FDIM  64    // number of nodes
#define HH    4     // heads
#define DOUT  128   // out window per head

// Scratch (device globals; allocation-free)
__device__ float g_fs[BB * HH * FDIM * DOUT];   // [b][h][i][d]
__device__ float g_fd[BB * HH * FDIM * DOUT];   // [b][h][j][d]
__device__ float g_oh[BB * HH * FDIM * DOUT];   // [b][h][j][d] per-head outputs

// ---------------------------------------------------------------------------
// f32x2 packed-math helpers (Blackwell FFMA2 path — PTX only).
// ---------------------------------------------------------------------------
__device__ __forceinline__ ull fma2(ull a, ull b, ull c) {
    asm("fma.rn.f32x2 %0, %1, %2, %0;" : "+l"(c) : "l"(a), "l"(b));
    return c;
}
__device__ __forceinline__ ull add2(ull a, ull b) {
    ull d; asm("add.rn.f32x2 %0, %1, %2;" : "=l"(d) : "l"(a), "l"(b));
    return d;
}
__device__ __forceinline__ ull dup2(float x) {
    ull d; asm("mov.b64 %0, {%1, %1};" : "=l"(d) : "f"(x));
    return d;
}
__device__ __forceinline__ float2 u2f(ull v) {
    float2 f; asm("mov.b64 {%0, %1}, %2;" : "=f"(f.x), "=f"(f.y) : "l"(v));
    return f;
}
__device__ __forceinline__ ull abs2(ull v) {          // 2x LOP3 on alu pipe
    return v & 0x7fffffff7fffffffULL;
}

// ---------------------------------------------------------------------------
// Kernel 1: projections via FFMA2, K split into 2 stages of 64 to halve
// smem (48 KB) and raise occupancy to 4 CTAs/SM.
// grid (64, 8): ctile 0..3 -> fs head=ct, 4..7 -> fd head=ct-4.
// CTA tile: 64 rows (i) x 128 cols (d).  Thread tile: 8 rows x 4 cols
// with row-pair-packed accumulators (16 FFMA2 per k).
// ---------------------------------------------------------------------------
__global__ __launch_bounds__(256, 4)
void proj_kernel(const float* __restrict__ x,
                 const float* __restrict__ Wsrc, const float* __restrict__ bsrc,
                 const float* __restrict__ Wdst, const float* __restrict__ bdst)
{
    extern __shared__ float sm[];
    float* As = sm;              // [64 k][64 r]   (16 KB)
    float* Bs = sm + 64 * 64;    // [64 k][128 c]  (32 KB)

    const int b  = blockIdx.x;
    const int ct = blockIdx.y;
    const int t  = threadIdx.x;

    const float* Wmat = (ct < 4) ? Wsrc : Wdst;
    const float* bias = (ct < 4) ? bsrc : bdst;
    const int c0 = (ct & 3) * 128;

    const int cx = t & 31;        // 32 col-threads * 4 cols = 128 cols
    const int ry = t >> 5;        // 8 row-threads (= warp id) * 8 rows = 64 rows
    // A loads: warp-broadcast LDS.128.  B loads: 16B/lane stride, conflict-free.

    ull acc2[4][4];               // [row-pair][col], lo = even row, hi = odd
    #pragma unroll
    for (int rp = 0; rp < 4; rp++)
        #pragma unroll
        for (int c = 0; c < 4; c++) acc2[rp][c] = 0ULL;

    #pragma unroll
    for (int ks = 0; ks < 2; ks++) {
        // Stage A: x[b] is [128 w][64 f]; rows w in [ks*64, ks*64+64)
        {
            const float4* xb  = (const float4*)(x + (size_t)b * WDIM * FDIM) + ks * 1024;
            float4*       As4 = (float4*)As;
            #pragma unroll
            for (int idx = t; idx < 64 * 16; idx += 256) As4[idx] = xb[idx];
        }
        // Stage B transposed: Bs[k][c] = Wmat[c0+c][ks*64 + k]
        #pragma unroll
        for (int idx = t; idx < 128 * 16; idx += 256) {
            int c  = idx & 127;
            int kq = idx >> 7;   // 0..15
            float4 v = *(const float4*)(Wmat + (size_t)(c0 + c) * WDIM + ks * 64 + kq * 4);
            Bs[(kq * 4 + 0) * 128 + c] = v.x;
            Bs[(kq * 4 + 1) * 128 + c] = v.y;
            Bs[(kq * 4 + 2) * 128 + c] = v.z;
            Bs[(kq * 4 + 3) * 128 + c] = v.w;
        }
        __syncthreads();

        #pragma unroll 4
        for (int k = 0; k < 64; k++) {
            float4 a0 = *(const float4*)&As[k * 64 + ry * 8];
            float4 a1 = *(const float4*)&As[k * 64 + ry * 8 + 4];
            float4 bq = *(const float4*)&Bs[k * 128 + cx * 4];
            const ull* av0 = (const ull*)&a0;
            const ull* av1 = (const ull*)&a1;
            ull av[4] = { av0[0], av0[1], av1[0], av1[1] };
            ull bd[4] = { dup2(bq.x), dup2(bq.y), dup2(bq.z), dup2(bq.w) };
            #pragma unroll
            for (int rp = 0; rp < 4; rp++)
                #pragma unroll
                for (int c = 0; c < 4; c++)
                    acc2[rp][c] = fma2(av[rp], bd[c], acc2[rp][c]);
        }
        __syncthreads();
    }

    // Epilogue: unpack row pairs, add bias, store [b][h][i][d]
    float* outbase = ((ct < 4) ? g_fs : g_fd)
                   + (size_t)b * HH * FDIM * DOUT + (size_t)(ct & 3) * FDIM * DOUT;
    float bv[4];
    #pragma unroll
    for (int c = 0; c < 4; c++) bv[c] = bias[c0 + cx * 4 + c];

    #pragma unroll
    for (int rp = 0; rp < 4; rp++) {
        float2 p0 = u2f(acc2[rp][0]);
        float2 p1 = u2f(acc2[rp][1]);
        float2 p2 = u2f(acc2[rp][2]);
        float2 p3 = u2f(acc2[rp][3]);
        int r_lo = ry * 8 + 2 * rp;
        float* row0 = outbase + (size_t)r_lo * DOUT + cx * 4;
        float* row1 = row0 + DOUT;
        *(float4*)row0 = make_float4(p0.x + bv[0], p1.x + bv[1], p2.x + bv[2], p3.x + bv[3]);
        *(float4*)row1 = make_float4(p0.y + bv[0], p1.y + bv[1], p2.y + bv[2], p3.y + bv[3]);
    }
}

// ---------------------------------------------------------------------------
// Kernel 2: fused scores + softmax + aggregation.
// One CTA per (b, h, j-half): 512 small CTAs (balanced), 32 dst nodes each.
//
// Exact rewrite: sum_d a_d * lrelu(fs_id + fd_jd, 0.2)
//              = 0.6*(As[i] + Ad[j]) + sum_d (0.4*a_d) * |fs_id + fd_jd|
// d packed into f32x2 pairs; softmax probs kept in registers; aggregation
// reads them via __shfl_sync (no prob smem, no extra sync).
// ---------------------------------------------------------------------------
#define NSTRIDE 130
#define JT      32      // j's per CTA

__global__ __launch_bounds__(256, 4)
void attn_kernel(const float* __restrict__ attn)
{
    extern __shared__ float sm[];
    float* fsN   = sm;                     // [64 i][130]
    float* fdN   = fsN + FDIM * NSTRIDE;   // [32 jloc][130]
    float* attn4 = fdN + JT * NSTRIDE;     // 128  (0.4 * attn[h])
    float* attnv = attn4 + 128;            // 128
    float* As_s  = attnv + 128;            // 64
    float* Ad_s  = As_s + 64;              // 32

    const int bh   = blockIdx.x >> 1;      // b*4 + h
    const int jb0  = (blockIdx.x & 1) * JT;
    const int h    = bh & 3;
    const int t    = threadIdx.x;
    const int lane = t & 31;
    const int w    = t >> 5;

    const float* fs = g_fs + (size_t)bh * FDIM * DOUT;
    const float* fd = g_fd + (size_t)bh * FDIM * DOUT;

    // Stage fs (all 64 i) and fd (32 local j), 8-byte chunks (NSTRIDE*4 % 8 == 0)
    for (int p = t; p < FDIM * 64; p += 256) {          // 64 ull per row
        int i = p >> 6, dp = p & 63;
        *(ull*)&fsN[i * NSTRIDE + 2 * dp] = *(const ull*)&fs[i * DOUT + 2 * dp];
    }
    for (int p = t; p < JT * 64; p += 256) {
        int j = p >> 6, dp = p & 63;
        *(ull*)&fdN[j * NSTRIDE + 2 * dp] = *(const ull*)&fd[(jb0 + j) * DOUT + 2 * dp];
    }
    if (t < 128) {
        float a = attn[h * 128 + t];
        attnv[t] = a;
        attn4[t] = 0.4f * a;
    }
    __syncthreads();

    // As[i] = sum_d attn[d]*fs[i,d];  Ad[jloc] likewise
    if (t < 64) {
        float s = 0.f;
        #pragma unroll 4
        for (int d = 0; d < 128; d++) s = fmaf(attnv[d], fsN[t * NSTRIDE + d], s);
        As_s[t] = s;
    } else if (t < 96) {
        int j = t - 64;
        float s = 0.f;
        #pragma unroll 4
        for (int d = 0; d < 128; d++) s = fmaf(attnv[d], fdN[j * NSTRIDE + d], s);
        Ad_s[j] = s;
    }
    __syncthreads();

    // ---- Score phase: warp w owns jloc = w*4..w*4+3; lane owns i = lane, lane+32.
    const int jl0 = w * 4;
    const int i0 = lane, i1 = lane + 32;
    ull acc0[4], acc1[4];
    #pragma unroll
    for (int jj = 0; jj < 4; jj++) { acc0[jj] = 0ULL; acc1[jj] = 0ULL; }

    #pragma unroll 4
    for (int dp = 0; dp < 64; dp++) {
        ull a42 = *(const ull*)&attn4[2 * dp];               // broadcast
        ull f20 = *(const ull*)&fsN[i0 * NSTRIDE + 2 * dp];
        ull f21 = *(const ull*)&fsN[i1 * NSTRIDE + 2 * dp];
        #pragma unroll
        for (int jj = 0; jj < 4; jj++) {
            ull fd2 = *(const ull*)&fdN[(jl0 + jj) * NSTRIDE + 2 * dp];  // broadcast
            acc0[jj] = fma2(a42, abs2(add2(f20, fd2)), acc0[jj]);
            acc1[jj] = fma2(a42, abs2(add2(f21, fd2)), acc1[jj]);
        }
    }

    // ---- Softmax over i (64 sources) per j; probs stay in registers
    const float As0 = As_s[i0], As1 = As_s[i1];
    float p0[4], p1[4];
    #pragma unroll
    for (int jj = 0; jj < 4; jj++) {
        float Adv = Ad_s[jl0 + jj];
        float2 h0 = u2f(acc0[jj]);
        float2 h1 = u2f(acc1[jj]);
        float s0 = 0.6f * (As0 + Adv) + (h0.x + h0.y);
        float s1 = 0.6f * (As1 + Adv) + (h1.x + h1.y);
        float m = fmaxf(s0, s1);
        #pragma unroll
        for (int o = 16; o; o >>= 1) m = fmaxf(m, __shfl_xor_sync(0xffffffffu, m, o));
        float e0 = __expf(s0 - m);
        float e1 = __expf(s1 - m);
        float ssum = e0 + e1;
        #pragma unroll
        for (int o = 16; o; o >>= 1) ssum += __shfl_xor_sync(0xffffffffu, ssum, o);
        float inv = __frcp_rn(ssum);
        p0[jj] = e0 * inv;
        p1[jj] = e1 * inv;
    }

    // ---- Aggregation: lane owns d-pairs at 2*lane and 2*(lane+32).
    // p[i] for i<32 lives in lane i reg p0; for i>=32 in lane i-32 reg p1.
    ull o2[4][2];
    #pragma unroll
    for (int jj = 0; jj < 4; jj++) { o2[jj][0] = 0ULL; o2[jj][1] = 0ULL; }

    #pragma unroll 4
    for (int i = 0; i < 64; i++) {
        ull f20 = *(const ull*)&fsN[i * NSTRIDE + 2 * lane];
        ull f21 = *(const ull*)&fsN[i * NSTRIDE + 2 * (lane + 32)];
        #pragma unroll
        for (int jj = 0; jj < 4; jj++) {
            float pv = (i < 32) ? p0[jj] : p1[jj];
            ull pd = dup2(__shfl_sync(0xffffffffu, pv, i & 31));
            o2[jj][0] = fma2(pd, f20, o2[jj][0]);
            o2[jj][1] = fma2(pd, f21, o2[jj][1]);
        }
    }

    float* oh = g_oh + (size_t)bh * FDIM * DOUT;
    #pragma unroll
    for (int jj = 0; jj < 4; jj++) {
        *(float2*)&oh[(jb0 + jl0 + jj) * DOUT + 2 * lane]        = u2f(o2[jj][0]);
        *(float2*)&oh[(jb0 + jl0 + jj) * DOUT + 2 * (lane + 32)] = u2f(o2[jj][1]);
    }
}

// ---------------------------------------------------------------------------
// Kernel 3: mean over heads + transpose.  out[b, d, j] = 0.25 * sum_h oh[b,h,j,d]
// ---------------------------------------------------------------------------
__global__ __launch_bounds__(256)
void reduce_kernel(float* __restrict__ out)
{
    __shared__ float s[64 * 129];
    const int b = blockIdx.x;
    const int t = threadIdx.x;
    const float* oh = g_oh + (size_t)b * HH * FDIM * DOUT;

    for (int idx = t; idx < FDIM * DOUT; idx += 256) {
        int j = idx >> 7, d = idx & 127;
        float v = oh[idx] + oh[idx + 8192] + oh[idx + 16384] + oh[idx + 24576];
        s[j * 129 + d] = 0.25f * v;
    }
    __syncthreads();

    float* ob = out + (size_t)b * DOUT * FDIM;
    for (int idx = t; idx < DOUT * FDIM; idx += 256) {
        int j = idx & 63, d = idx >> 6;
        ob[idx] = s[j * 129 + d];
    }
}

// ---------------------------------------------------------------------------
extern "C" void kernel_launch(void* const* d_in, const int* in_sizes, int n_in,
                              void* d_out, int out_size)
{
    const float* x    = (const float*)d_in[0];
    const float* Wsrc = (const float*)d_in[1];
    const float* bsrc = (const float*)d_in[2];
    const float* Wdst = (const float*)d_in[3];
    const float* bdst = (const float*)d_in[4];
    const float* attn = (const float*)d_in[5];
    float* out = (float*)d_out;

    const int smem1 = (64 * 64 + 64 * 128) * 4;                                   // 48 KB
    const int smem2 = ((FDIM + JT) * NSTRIDE + 128 + 128 + 64 + 32) * 4;          // ~51.3 KB

    cudaFuncSetAttribute(proj_kernel, cudaFuncAttributeMaxDynamicSharedMemorySize, smem1);
    cudaFuncSetAttribute(attn_kernel, cudaFuncAttributeMaxDynamicSharedMemorySize, smem2);

    proj_kernel<<<dim3(BB, 8), 256, smem1>>>(x, Wsrc, bsrc, Wdst, bdst);
    attn_kernel<<<BB * HH * 2, 256, smem2>>>(attn);
    reduce_kernel<<<BB, 256>>>(out);
}

// round 8
// speedup vs baseline: 1.1281x; 1.1281x over previous
#include <cuda_runtime.h>

typedef unsigned long long ull;

// Problem constants
#define BB    64    // batch
#define WDIM  128   // node feature dim (K of projection)
#define FDIM  64    // number of nodes
#define HH    4     // heads
#define DOUT  128   // out window per head

// Scratch (device globals; allocation-free)
__device__ float g_fs[BB * HH * FDIM * DOUT];   // [b][h][i][d]
__device__ float g_fd[BB * HH * FDIM * DOUT];   // [b][h][j][d]
__device__ float g_oh[BB * HH * FDIM * DOUT];   // [b][h][j][d] per-head outputs

// ---------------------------------------------------------------------------
// f32x2 packed-math helpers (Blackwell FFMA2 path — PTX only).
// ---------------------------------------------------------------------------
__device__ __forceinline__ ull fma2(ull a, ull b, ull c) {
    asm("fma.rn.f32x2 %0, %1, %2, %0;" : "+l"(c) : "l"(a), "l"(b));
    return c;
}
__device__ __forceinline__ ull add2(ull a, ull b) {
    ull d; asm("add.rn.f32x2 %0, %1, %2;" : "=l"(d) : "l"(a), "l"(b));
    return d;
}
__device__ __forceinline__ ull dup2(float x) {
    ull d; asm("mov.b64 %0, {%1, %1};" : "=l"(d) : "f"(x));
    return d;
}
__device__ __forceinline__ float2 u2f(ull v) {
    float2 f; asm("mov.b64 {%0, %1}, %2;" : "=f"(f.x), "=f"(f.y) : "l"(v));
    return f;
}
__device__ __forceinline__ ull abs2(ull v) {          // 2x LOP3 on alu pipe
    return v & 0x7fffffff7fffffffULL;
}

// ---------------------------------------------------------------------------
// Kernel 1: projections via FFMA2, single 96 KB stage (K=128 resident).
// grid (64, 8): ctile 0..3 -> fs head=ct, 4..7 -> fd head=ct-4.
// CTA tile: 64 rows (i) x 128 cols (d).
// Thread tile: 16 rows x 2 cols (row-pair packed accumulators):
//   per k: 16 FFMA2, 2 dups (4 MOV), 4 broadcast LDS.128 (A) + 1 LDS.64 (B).
// 256 threads = 4 row-groups x 64 col-threads; lanes in a warp share the
// row-group -> A loads are warp-broadcast; B LDS.64 is conflict-free.
// ---------------------------------------------------------------------------
__global__ __launch_bounds__(256, 2)
void proj_kernel(const float* __restrict__ x,
                 const float* __restrict__ Wsrc, const float* __restrict__ bsrc,
                 const float* __restrict__ Wdst, const float* __restrict__ bdst)
{
    extern __shared__ float sm[];
    float* As = sm;               // [128 k][64 r]   (32 KB)
    float* Bs = sm + 128 * 64;    // [128 k][128 c]  (64 KB)

    const int b  = blockIdx.x;
    const int ct = blockIdx.y;
    const int t  = threadIdx.x;

    const float* Wmat = (ct < 4) ? Wsrc : Wdst;
    const float* bias = (ct < 4) ? bsrc : bdst;
    const int c0 = (ct & 3) * 128;

    // Load A: x[b] is [128 w][64 f] contiguous -> As[w][f] directly
    {
        const float4* xb  = (const float4*)(x + (size_t)b * WDIM * FDIM);
        float4*       As4 = (float4*)As;
        #pragma unroll
        for (int idx = t; idx < 128 * 16; idx += 256) As4[idx] = xb[idx];
    }
    // Load B transposed: Bs[k][c] = Wmat[c0+c][k]
    for (int idx = t; idx < 128 * 32; idx += 256) {
        int c  = idx & 127;
        int kq = idx >> 7;
        float4 v = *(const float4*)(Wmat + (size_t)(c0 + c) * WDIM + kq * 4);
        Bs[(kq * 4 + 0) * 128 + c] = v.x;
        Bs[(kq * 4 + 1) * 128 + c] = v.y;
        Bs[(kq * 4 + 2) * 128 + c] = v.z;
        Bs[(kq * 4 + 3) * 128 + c] = v.w;
    }
    __syncthreads();

    const int ct6 = t & 63;       // 64 col-threads * 2 cols = 128 cols
    const int rt  = t >> 6;       // 4 row-groups * 16 rows = 64 rows
    const int r0  = rt * 16;
    const int cc  = ct6 * 2;

    ull acc2[8][2];               // [row-pair][col], lo = even row, hi = odd
    #pragma unroll
    for (int rp = 0; rp < 8; rp++) { acc2[rp][0] = 0ULL; acc2[rp][1] = 0ULL; }

    #pragma unroll 4
    for (int k = 0; k < 128; k++) {
        float4 a0 = *(const float4*)&As[k * 64 + r0];
        float4 a1 = *(const float4*)&As[k * 64 + r0 + 4];
        float4 a2 = *(const float4*)&As[k * 64 + r0 + 8];
        float4 a3 = *(const float4*)&As[k * 64 + r0 + 12];
        float2 bq = *(const float2*)&Bs[k * 128 + cc];
        ull bd0 = dup2(bq.x);
        ull bd1 = dup2(bq.y);
        const ull* p0 = (const ull*)&a0;
        const ull* p1 = (const ull*)&a1;
        const ull* p2 = (const ull*)&a2;
        const ull* p3 = (const ull*)&a3;
        ull av[8] = { p0[0], p0[1], p1[0], p1[1], p2[0], p2[1], p3[0], p3[1] };
        #pragma unroll
        for (int rp = 0; rp < 8; rp++) {
            acc2[rp][0] = fma2(av[rp], bd0, acc2[rp][0]);
            acc2[rp][1] = fma2(av[rp], bd1, acc2[rp][1]);
        }
    }

    // Epilogue: unpack row pairs, add bias, store [b][h][i][d]
    float* outbase = ((ct < 4) ? g_fs : g_fd)
                   + (size_t)b * HH * FDIM * DOUT + (size_t)(ct & 3) * FDIM * DOUT;
    const float bv0 = bias[c0 + cc];
    const float bv1 = bias[c0 + cc + 1];

    #pragma unroll
    for (int rp = 0; rp < 8; rp++) {
        float2 q0 = u2f(acc2[rp][0]);   // col cc:   {row even, row odd}
        float2 q1 = u2f(acc2[rp][1]);   // col cc+1: {row even, row odd}
        float* rowA = outbase + (size_t)(r0 + 2 * rp) * DOUT + cc;
        float* rowB = rowA + DOUT;
        *(float2*)rowA = make_float2(q0.x + bv0, q1.x + bv1);
        *(float2*)rowB = make_float2(q0.y + bv0, q1.y + bv1);
    }
}

// ---------------------------------------------------------------------------
// Kernel 2: fused scores + softmax + aggregation, one CTA per (b,h).
//
// Exact rewrite: sum_d a_d * lrelu(fs_id + fd_jd, 0.2)
//              = 0.6*(As[i] + Ad[j]) + sum_d (0.4*a_d) * |fs_id + fd_jd|
// The |.| sum uses d packed into f32x2 pairs (halves summed at the end):
// ADD2 + FFMA2 on the fma pipe, abs via 64-bit AND (LOP3) on the alu pipe.
// smem: fsN/fdN row-major [i][d] stride 130 (8B-aligned packed LDS.64).
// ---------------------------------------------------------------------------
#define NSTRIDE 130

__global__ __launch_bounds__(256, 2)
void attn_kernel(const float* __restrict__ attn)
{
    extern __shared__ float sm[];
    float* fsN   = sm;                     // [64 i][130]
    float* fdN   = fsN + FDIM * NSTRIDE;   // [64 j][130]
    float* attn4 = fdN + FDIM * NSTRIDE;   // 128  (0.4 * attn[h])
    float* attnv = attn4 + 128;            // 128
    float* As_s  = attnv + 128;            // 64
    float* Ad_s  = As_s + 64;              // 64
    float* prob  = Ad_s + 64;              // [64 j][64 i]

    const int bh   = blockIdx.x;           // b*4 + h
    const int h    = bh & 3;
    const int t    = threadIdx.x;
    const int lane = t & 31;
    const int w    = t >> 5;

    const float* fs = g_fs + (size_t)bh * FDIM * DOUT;
    const float* fd = g_fd + (size_t)bh * FDIM * DOUT;

    // Stage fs/fd (row-major, padded stride), 8-byte chunks
    for (int p = t; p < FDIM * 64; p += 256) {     // 64 ull per row
        int i = p >> 6, dp = p & 63;
        *(ull*)&fsN[i * NSTRIDE + 2 * dp] = *(const ull*)&fs[i * DOUT + 2 * dp];
        *(ull*)&fdN[i * NSTRIDE + 2 * dp] = *(const ull*)&fd[i * DOUT + 2 * dp];
    }
    if (t < 128) {
        float a = attn[h * 128 + t];
        attnv[t] = a;
        attn4[t] = 0.4f * a;
    }
    __syncthreads();

    // As[i] = sum_d attn[d]*fs[i,d];  Ad[j] likewise
    if (t < 64) {
        float s = 0.f;
        #pragma unroll 4
        for (int d = 0; d < 128; d++) s = fmaf(attnv[d], fsN[t * NSTRIDE + d], s);
        As_s[t] = s;
    } else if (t < 128) {
        int j = t - 64;
        float s = 0.f;
        #pragma unroll 4
        for (int d = 0; d < 128; d++) s = fmaf(attnv[d], fdN[j * NSTRIDE + d], s);
        Ad_s[j] = s;
    }
    __syncthreads();

    // ---- Score phase: warp w owns j = w*8..w*8+7; lane owns i = lane, lane+32.
    const int jb = w * 8;
    const int i0 = lane, i1 = lane + 32;
    ull acc0[8], acc1[8];
    #pragma unroll
    for (int jj = 0; jj < 8; jj++) { acc0[jj] = 0ULL; acc1[jj] = 0ULL; }

    #pragma unroll 2
    for (int dp = 0; dp < 64; dp++) {
        ull a42 = *(const ull*)&attn4[2 * dp];               // broadcast
        ull f20 = *(const ull*)&fsN[i0 * NSTRIDE + 2 * dp];
        ull f21 = *(const ull*)&fsN[i1 * NSTRIDE + 2 * dp];
        #pragma unroll
        for (int jj = 0; jj < 8; jj++) {
            ull fd2 = *(const ull*)&fdN[(jb + jj) * NSTRIDE + 2 * dp];  // broadcast
            acc0[jj] = fma2(a42, abs2(add2(f20, fd2)), acc0[jj]);
            acc1[jj] = fma2(a42, abs2(add2(f21, fd2)), acc1[jj]);
        }
    }

    // ---- Softmax over i (64 sources) per j
    const float As0 = As_s[i0], As1 = As_s[i1];
    #pragma unroll
    for (int jj = 0; jj < 8; jj++) {
        float Adv = Ad_s[jb + jj];
        float2 h0 = u2f(acc0[jj]);
        float2 h1 = u2f(acc1[jj]);
        float s0 = 0.6f * (As0 + Adv) + (h0.x + h0.y);
        float s1 = 0.6f * (As1 + Adv) + (h1.x + h1.y);
        float m = fmaxf(s0, s1);
        #pragma unroll
        for (int o = 16; o; o >>= 1) m = fmaxf(m, __shfl_xor_sync(0xffffffffu, m, o));
        float e0 = __expf(s0 - m);
        float e1 = __expf(s1 - m);
        float ssum = e0 + e1;
        #pragma unroll
        for (int o = 16; o; o >>= 1) ssum += __shfl_xor_sync(0xffffffffu, ssum, o);
        float inv = __frcp_rn(ssum);
        prob[(jb + jj) * 64 + i0] = e0 * inv;
        prob[(jb + jj) * 64 + i1] = e1 * inv;
    }
    __syncwarp();

    // ---- Aggregation: lane owns d-pairs at 2*lane and 2*(lane+32),
    // 8 j's register-blocked; prob read via broadcast LDS.
    ull o2[8][2];
    #pragma unroll
    for (int jj = 0; jj < 8; jj++) { o2[jj][0] = 0ULL; o2[jj][1] = 0ULL; }

    #pragma unroll 2
    for (int i = 0; i < 64; i++) {
        ull f20 = *(const ull*)&fsN[i * NSTRIDE + 2 * lane];
        ull f21 = *(const ull*)&fsN[i * NSTRIDE + 2 * (lane + 32)];
        #pragma unroll
        for (int jj = 0; jj < 8; jj++) {
            ull pd = dup2(prob[(jb + jj) * 64 + i]);   // broadcast + dup
            o2[jj][0] = fma2(pd, f20, o2[jj][0]);
            o2[jj][1] = fma2(pd, f21, o2[jj][1]);
        }
    }

    float* oh = g_oh + (size_t)bh * FDIM * DOUT;
    #pragma unroll
    for (int jj = 0; jj < 8; jj++) {
        *(float2*)&oh[(jb + jj) * DOUT + 2 * lane]        = u2f(o2[jj][0]);
        *(float2*)&oh[(jb + jj) * DOUT + 2 * (lane + 32)] = u2f(o2[jj][1]);
    }
}

// ---------------------------------------------------------------------------
// Kernel 3: mean over heads + transpose.  out[b, d, j] = 0.25 * sum_h oh[b,h,j,d]
// ---------------------------------------------------------------------------
__global__ __launch_bounds__(256)
void reduce_kernel(float* __restrict__ out)
{
    __shared__ float s[64 * 129];
    const int b = blockIdx.x;
    const int t = threadIdx.x;
    const float* oh = g_oh + (size_t)b * HH * FDIM * DOUT;

    for (int idx = t; idx < FDIM * DOUT; idx += 256) {
        int j = idx >> 7, d = idx & 127;
        float v = oh[idx] + oh[idx + 8192] + oh[idx + 16384] + oh[idx + 24576];
        s[j * 129 + d] = 0.25f * v;
    }
    __syncthreads();

    float* ob = out + (size_t)b * DOUT * FDIM;
    for (int idx = t; idx < DOUT * FDIM; idx += 256) {
        int j = idx & 63, d = idx >> 6;
        ob[idx] = s[j * 129 + d];
    }
}

// ---------------------------------------------------------------------------
extern "C" void kernel_launch(void* const* d_in, const int* in_sizes, int n_in,
                              void* d_out, int out_size)
{
    const float* x    = (const float*)d_in[0];
    const float* Wsrc = (const float*)d_in[1];
    const float* bsrc = (const float*)d_in[2];
    const float* Wdst = (const float*)d_in[3];
    const float* bdst = (const float*)d_in[4];
    const float* attn = (const float*)d_in[5];
    float* out = (float*)d_out;

    const int smem1 = (128 * 64 + 128 * 128) * 4;                               // 96 KB
    const int smem2 = (2 * FDIM * NSTRIDE + 128 + 128 + 64 + 64 + 4096) * 4;    // 84480 B

    cudaFuncSetAttribute(proj_kernel, cudaFuncAttributeMaxDynamicSharedMemorySize, smem1);
    cudaFuncSetAttribute(attn_kernel, cudaFuncAttributeMaxDynamicSharedMemorySize, smem2);

    proj_kernel<<<dim3(BB, 8), 256, smem1>>>(x, Wsrc, bsrc, Wdst, bdst);
    attn_kernel<<<BB * HH, 256, smem2>>>(attn);
    reduce_kernel<<<BB, 256>>>(out);
}